// round 14
// baseline (speedup 1.0000x reference)
#include <cuda_runtime.h>

#define TT      65536
#define HID     128
#define G3      384
#define INS     96
#define LIN     32
#define CHUNK   8
#define NCHUNK  (TT / CHUNK)   // 8192
#define NPROD   147
#define NBLK    (NPROD + 1)    // 148
#define NT      768

#define IG_CHUNK_F  (CHUNK * G3)                 // 3072 floats
#define XL_CHUNK_F  (CHUNK * LIN)                // 256 floats
#define IG_CHUNK_BYTES (IG_CHUNK_F * 4)          // 12288
#define XL_CHUNK_BYTES (XL_CHUNK_F * 4)          // 1024
#define TX_BYTES       (IG_CHUNK_BYTES + XL_CHUNK_BYTES)

// 96 MB scratch for precomputed input gates, + chunk-ready flags
__device__ float g_ig[TT * G3];
__device__ int   g_flag[NCHUNK];

// ---------- f32x2 helpers ----------
static __device__ __forceinline__ unsigned long long pk2(float a, float b) {
    unsigned long long r;
    asm("mov.b64 %0, {%1,%2};" : "=l"(r) : "f"(a), "f"(b));
    return r;
}
static __device__ __forceinline__ void fma2(unsigned long long& d,
                                            unsigned long long a,
                                            unsigned long long b) {
    asm("fma.rn.f32x2 %0, %1, %2, %0;" : "+l"(d) : "l"(a), "l"(b));
}
static __device__ __forceinline__ unsigned long long add2(unsigned long long a,
                                                          unsigned long long b) {
    unsigned long long r;
    asm("add.rn.f32x2 %0, %1, %2;" : "=l"(r) : "l"(a), "l"(b));
    return r;
}
static __device__ __forceinline__ float lo_hi_sum(unsigned long long v) {
    float lo, hi;
    asm("mov.b64 {%0,%1}, %2;" : "=f"(lo), "=f"(hi) : "l"(v));
    return lo + hi;
}

// ---------- single-MUFU nonlinearities ----------
static __device__ __forceinline__ float tanh_fast(float x) {
    float r; asm("tanh.approx.f32 %0, %1;" : "=f"(r) : "f"(x)); return r;
}
static __device__ __forceinline__ float sigmoid_f(float x) {
    // sigma(x) = 0.5*tanh(x/2) + 0.5   (1 MUFU + 2 FMA)
    return fmaf(0.5f, tanh_fast(0.5f * x), 0.5f);
}

// ---------- sync / async primitives ----------
static __device__ __forceinline__ void wait_flag(const int* fp) {
    int f;
    do { asm volatile("ld.acquire.gpu.global.b32 %0, [%1];" : "=r"(f) : "l"(fp)); } while (f == 0);
}
static __device__ __forceinline__ int ld_relaxed(const int* fp) {
    int f;
    asm volatile("ld.relaxed.gpu.global.b32 %0, [%1];" : "=r"(f) : "l"(fp));
    return f;
}
static __device__ __forceinline__ unsigned smem_u32(const void* p) {
    unsigned a;
    asm("{ .reg .u64 t; cvta.to.shared.u64 t, %1; cvt.u32.u64 %0, t; }" : "=r"(a) : "l"(p));
    return a;
}
static __device__ __forceinline__ void mbar_init(unsigned mbar, unsigned cnt) {
    asm volatile("mbarrier.init.shared.b64 [%0], %1;" :: "r"(mbar), "r"(cnt) : "memory");
}
static __device__ __forceinline__ void mbar_expect_tx(unsigned mbar, unsigned bytes) {
    asm volatile("mbarrier.arrive.expect_tx.shared.b64 _, [%0], %1;" :: "r"(mbar), "r"(bytes) : "memory");
}
static __device__ __forceinline__ void mbar_wait(unsigned mbar, unsigned parity) {
    asm volatile(
        "{\n\t.reg .pred P;\n\t"
        "W%=:\n\t"
        "mbarrier.try_wait.parity.shared::cta.b64 P, [%0], %1;\n\t"
        "@!P bra W%=;\n\t}"
        :: "r"(mbar), "r"(parity) : "memory");
}
static __device__ __forceinline__ void bulk_g2s(unsigned dst, const void* src,
                                                unsigned bytes, unsigned mbar) {
    asm volatile(
        "cp.async.bulk.shared::cta.global.mbarrier::complete_tx::bytes [%0], [%1], %2, [%3];"
        :: "r"(dst), "l"(src), "r"(bytes), "r"(mbar) : "memory");
}

// ---------- clear flags each launch (graph-replay safe) ----------
__global__ void gru_clear_flags() {
    int i = blockIdx.x * blockDim.x + threadIdx.x;
    if (i < NCHUNK) g_flag[i] = 0;
}

// scan-block shared float carve:
//  [0 .. 6144)      igates double buffer: 2 x 8 x 384
//  [6144 .. 6656)   x_lin  double buffer: 2 x 8 x 32
//  [6656 .. 6784)   sh_h   (128 floats, single buffer)
//  [6784 .. 7552)   s_part (768 partials: index = gaterow*2 + khalf)
//  producer branch reuses [0 .. 864) for x staging

__global__ __launch_bounds__(NT, 1)
void gru_fused(const float* __restrict__ x_gru,   // (T, 96)
               const float* __restrict__ x_lin,   // (T, 32)
               const float* __restrict__ h_init,  // (128,)
               const float* __restrict__ w_ih,    // (384, 96)
               const float* __restrict__ w_hh,    // (384, 128)
               const float* __restrict__ b_ih,    // (384,)
               const float* __restrict__ b_nv,    // (128,)
               const float* __restrict__ lbias_p, // (1,)
               float* __restrict__ out)           // (T, 1)
{
    __shared__ __align__(16) float sm[7552];
    __shared__ __align__(8) unsigned long long mbar_storage;
    const int tid = threadIdx.x;

    if (blockIdx.x != 0) {
        // ======== PRODUCER: igates = x_gru @ w_ih.T + b_ih (row, k-half split) ========
        const int b    = blockIdx.x - 1;   // 0..146
        const int prow = tid >> 1;         // 0..383
        const int kh   = tid & 1;          // k-half (48 each)
        float wreg[48];
        {
            const float* wp = w_ih + prow * INS + kh * 48;
            #pragma unroll
            for (int j = 0; j < 48; j++) wreg[j] = wp[j];
        }
        const float bih = (kh == 0) ? b_ih[prow] : 0.0f;

        for (int c = b; c < NCHUNK; c += NPROD) {
            const int t0 = c * CHUNK;
            __syncthreads();  // smem reuse guard across chunks
            for (int i = tid; i < CHUNK * INS; i += NT) {
                int ttl = i / INS, k = i % INS;
                sm[k * 9 + ttl] = x_gru[(size_t)(t0 + ttl) * INS + k];
            }
            __syncthreads();
            {
                float acc[CHUNK];
                #pragma unroll
                for (int ttl = 0; ttl < CHUNK; ttl++) acc[ttl] = bih;
                #pragma unroll 8
                for (int j = 0; j < 48; j++) {
                    const float w = wreg[j];
                    const float* xs = &sm[(kh * 48 + j) * 9];
                    #pragma unroll
                    for (int ttl = 0; ttl < CHUNK; ttl++)
                        acc[ttl] = fmaf(w, xs[ttl], acc[ttl]);
                }
                #pragma unroll
                for (int ttl = 0; ttl < CHUNK; ttl++)
                    acc[ttl] += __shfl_xor_sync(0xffffffffu, acc[ttl], 1);
                if (kh == 0) {
                    #pragma unroll
                    for (int ttl = 0; ttl < CHUNK; ttl++)
                        g_ig[(size_t)(t0 + ttl) * G3 + prow] = acc[ttl];
                }
            }
            __syncthreads();  // all stores issued before the release
            if (tid == 0) {
                __threadfence();
                atomicExch(&g_flag[c], 1);
            }
        }
        return;
    }

    // ============ SCAN: 768 threads, thread = (gate-row g, k-half kh) ============
    const int g    = tid >> 1;   // 0..383
    const int kh   = tid & 1;    // 64-wide K half
    const int lane = tid & 31;
    const bool is_outw = (tid >= 128 && tid < 160);  // warp 4: deferred output duty

    float* igb    = sm;          // [2][3072]
    float* xlb    = sm + 6144;   // [2][256]
    float* sh_h   = sm + 6656;   // 128
    float* s_part = sm + 6784;   // 768
    const unsigned mbar = smem_u32(&mbar_storage);

    // weights: one gate-row, one k-half: 32 f32x2
    unsigned long long w_[32];
    {
        const float2* wp = (const float2*)(w_hh + (size_t)g * HID) + kh * 32;
        #pragma unroll
        for (int j = 0; j < 32; j++) { float2 v = wp[j]; w_[j] = pk2(v.x, v.y); }
    }
    const float bn    = (tid < HID) ? b_nv[tid] : 0.0f;
    const float lbias = lbias_p[0];
    float h_reg = (tid < HID) ? h_init[tid] : 0.0f;   // rows: tid<128
    if (tid < HID) sh_h[tid] = h_reg;
    float xl_reg = 0.0f;                              // warp-4 lanes

    // prologue: init mbar, kick copy of chunk 0
    if (tid == 0) {
        mbar_init(mbar, 1);
        wait_flag(&g_flag[0]);
        mbar_expect_tx(mbar, TX_BYTES);
        bulk_g2s(smem_u32(igb), g_ig, IG_CHUNK_BYTES, mbar);
        bulk_g2s(smem_u32(xlb), x_lin, XL_CHUNK_BYTES, mbar);
    }
    int flag_pre = 0;

    auto step = [&](int t, int s, const float* ig, const float* xl) {
        // ---- matvec phase: all 768 threads, partial dot over 64 h values ----
        unsigned long long a0 = 0ull, a1 = 0ull;
        const ulonglong2* h2 = (const ulonglong2*)(sh_h + kh * 64);
        #pragma unroll 4
        for (int j = 0; j < 16; j++) {
            ulonglong2 v = h2[j];
            fma2(a0, w_[2 * j],     v.x);
            fma2(a1, w_[2 * j + 1], v.y);
        }
        // deferred output for t-1 on warp 4 (sh_h still holds h[t-1])
        if (is_outw) {
            if (t > 0) {
                float p = sh_h[lane] * xl_reg;
                p += __shfl_xor_sync(0xffffffffu, p, 1);
                p += __shfl_xor_sync(0xffffffffu, p, 2);
                p += __shfl_xor_sync(0xffffffffu, p, 4);
                p += __shfl_xor_sync(0xffffffffu, p, 8);
                p += __shfl_xor_sync(0xffffffffu, p, 16);
                if (lane == 0) out[t - 1] = p + lbias;
            }
            xl_reg = xl[s * LIN + lane];
        }
        s_part[tid] = lo_hi_sum(add2(a0, a1));
        __syncthreads();  // bar1: partials published, all sh_h reads done

        // ---- epilogue phase: threads 0..127 (one warp per SMSP) ----
        if (tid < HID) {
            float2 pr = *(const float2*)(s_part + 2 * tid);
            float2 pz = *(const float2*)(s_part + 2 * tid + 256);
            float2 pn = *(const float2*)(s_part + 2 * tid + 512);
            const float igr = ig[s * G3 + tid];
            const float igz = ig[s * G3 + 128 + tid];
            const float ign = ig[s * G3 + 256 + tid];
            const float r = sigmoid_f(pr.x + pr.y + igr);
            const float z = sigmoid_f(pz.x + pz.y + igz);
            const float n = tanh_fast(ign + r * (pn.x + pn.y + bn));
            const float hnew = fmaf(z, h_reg - n, n);
            h_reg = hnew;
            sh_h[tid] = hnew;
        }
        __syncthreads();  // bar2: new h visible
    };

    for (int c = 0; c < NCHUNK; c++) {
        const float* ig = igb + (c & 1) * IG_CHUNK_F;
        const float* xl = xlb + (c & 1) * XL_CHUNK_F;

        if (tid == 0) mbar_wait(mbar, (unsigned)(c & 1));  // chunk c copy complete
        __syncthreads();                                   // publish buffer

        if (tid == 0 && c + 1 < NCHUNK) {
            if (flag_pre) asm volatile("fence.acq_rel.gpu;" ::: "memory");
            else          wait_flag(&g_flag[c + 1]);
            mbar_expect_tx(mbar, TX_BYTES);
            bulk_g2s(smem_u32(igb + ((c + 1) & 1) * IG_CHUNK_F),
                     g_ig + (size_t)(c + 1) * IG_CHUNK_F, IG_CHUNK_BYTES, mbar);
            bulk_g2s(smem_u32(xlb + ((c + 1) & 1) * XL_CHUNK_F),
                     x_lin + (size_t)(c + 1) * XL_CHUNK_F, XL_CHUNK_BYTES, mbar);
            flag_pre = (c + 2 < NCHUNK) ? ld_relaxed(&g_flag[c + 2]) : 1;
        }

        const int t0 = c * CHUNK;
        #pragma unroll 1
        for (int s = 0; s < CHUNK; s++)
            step(t0 + s, s, ig, xl);
    }

    // final output: sh_h holds h[TT-1]; xl_reg = x_lin[TT-1] on warp 4
    if (is_outw) {
        float p = sh_h[lane] * xl_reg;
        p += __shfl_xor_sync(0xffffffffu, p, 1);
        p += __shfl_xor_sync(0xffffffffu, p, 2);
        p += __shfl_xor_sync(0xffffffffu, p, 4);
        p += __shfl_xor_sync(0xffffffffu, p, 8);
        p += __shfl_xor_sync(0xffffffffu, p, 16);
        if (lane == 0) out[TT - 1] = p + lbias;
    }
}

extern "C" void kernel_launch(void* const* d_in, const int* in_sizes, int n_in,
                              void* d_out, int out_size) {
    const float* x_gru = (const float*)d_in[0];  // (65536, 96)
    const float* x_lin = (const float*)d_in[1];  // (65536, 32)
    const float* h0    = (const float*)d_in[2];  // (128,)
    const float* w_ih  = (const float*)d_in[3];  // (384, 96)
    const float* w_hh  = (const float*)d_in[4];  // (384, 128)
    const float* b_ih  = (const float*)d_in[5];  // (384,)
    const float* b_n   = (const float*)d_in[6];  // (128,)
    const float* lb    = (const float*)d_in[7];  // (1,)
    float* out = (float*)d_out;                  // (65536, 1)

    gru_clear_flags<<<(NCHUNK + 255) / 256, 256>>>();
    gru_fused<<<NBLK, NT>>>(x_gru, x_lin, h0, w_ih, w_hh, b_ih, b_n, lb, out);
}

// round 16
// speedup vs baseline: 1.7231x; 1.7231x over previous
#include <cuda_runtime.h>

#define TT      65536
#define HID     128
#define G3      384
#define INS     96
#define LIN     32
#define IGW     512                              // padded igates row: [r,z,n,pad] x 128
#define CHUNK   8
#define NCHUNK  (TT / CHUNK)   // 8192
#define NPROD   147
#define NBLK    (NPROD + 1)    // 148
#define NT      1024

#define IG_CHUNK_F  (CHUNK * IGW)                // 4096 floats
#define XL_CHUNK_F  (CHUNK * LIN)                // 256 floats
#define IG_CHUNK_BYTES (IG_CHUNK_F * 4)          // 16384
#define XL_CHUNK_BYTES (XL_CHUNK_F * 4)          // 1024
#define TX_BYTES       (IG_CHUNK_BYTES + XL_CHUNK_BYTES)

// 128 MB scratch for precomputed (padded) input gates, + chunk-ready flags
__device__ float g_ig[(size_t)TT * IGW];
__device__ int   g_flag[NCHUNK];

// ---------- f32x2 helpers ----------
static __device__ __forceinline__ unsigned long long pk2(float a, float b) {
    unsigned long long r;
    asm("mov.b64 %0, {%1,%2};" : "=l"(r) : "f"(a), "f"(b));
    return r;
}
static __device__ __forceinline__ void fma2(unsigned long long& d,
                                            unsigned long long a,
                                            unsigned long long b) {
    asm("fma.rn.f32x2 %0, %1, %2, %0;" : "+l"(d) : "l"(a), "l"(b));
}
static __device__ __forceinline__ float lo_hi_sum(unsigned long long v) {
    float lo, hi;
    asm("mov.b64 {%0,%1}, %2;" : "=f"(lo), "=f"(hi) : "l"(v));
    return lo + hi;
}

// ---------- single-MUFU nonlinearities ----------
static __device__ __forceinline__ float tanh_fast(float x) {
    float r; asm("tanh.approx.f32 %0, %1;" : "=f"(r) : "f"(x)); return r;
}
// sigmoid on a PRE-HALVED argument: sigma(2u) = 0.5*tanh(u) + 0.5
static __device__ __forceinline__ float sigmoid_half(float u) {
    return fmaf(0.5f, tanh_fast(u), 0.5f);
}

// ---------- sync / async primitives ----------
static __device__ __forceinline__ void wait_flag(const int* fp) {
    int f;
    do { asm volatile("ld.acquire.gpu.global.b32 %0, [%1];" : "=r"(f) : "l"(fp)); } while (f == 0);
}
static __device__ __forceinline__ int ld_relaxed(const int* fp) {
    int f;
    asm volatile("ld.relaxed.gpu.global.b32 %0, [%1];" : "=r"(f) : "l"(fp));
    return f;
}
static __device__ __forceinline__ unsigned smem_u32(const void* p) {
    unsigned a;
    asm("{ .reg .u64 t; cvta.to.shared.u64 t, %1; cvt.u32.u64 %0, t; }" : "=r"(a) : "l"(p));
    return a;
}
static __device__ __forceinline__ void mbar_init(unsigned mbar, unsigned cnt) {
    asm volatile("mbarrier.init.shared.b64 [%0], %1;" :: "r"(mbar), "r"(cnt) : "memory");
}
static __device__ __forceinline__ void mbar_expect_tx(unsigned mbar, unsigned bytes) {
    asm volatile("mbarrier.arrive.expect_tx.shared.b64 _, [%0], %1;" :: "r"(mbar), "r"(bytes) : "memory");
}
static __device__ __forceinline__ void mbar_wait(unsigned mbar, unsigned parity) {
    asm volatile(
        "{\n\t.reg .pred P;\n\t"
        "W%=:\n\t"
        "mbarrier.try_wait.parity.shared::cta.b64 P, [%0], %1;\n\t"
        "@!P bra W%=;\n\t}"
        :: "r"(mbar), "r"(parity) : "memory");
}
static __device__ __forceinline__ void bulk_g2s(unsigned dst, const void* src,
                                                unsigned bytes, unsigned mbar) {
    asm volatile(
        "cp.async.bulk.shared::cta.global.mbarrier::complete_tx::bytes [%0], [%1], %2, [%3];"
        :: "r"(dst), "l"(src), "r"(bytes), "r"(mbar) : "memory");
}

// ---------- clear flags each launch (graph-replay safe) ----------
__global__ void gru_clear_flags() {
    int i = blockIdx.x * blockDim.x + threadIdx.x;
    if (i < NCHUNK) g_flag[i] = 0;
}

// scan-block shared float carve (9024 floats = 36.1 KB, under the 48 KB static limit):
//  [0 .. 8192)      igates double buffer: 2 x 8 x 512
//  [8192 .. 8704)   x_lin  double buffer: 2 x 8 x 32
//  [8704 .. 8864)   shA (padded h: element e at (e>>4)*20 + (e&15); 160 words)
//  [8864 .. 9024)   shB
//  producer branch reuses [0 .. 864) for x staging

__global__ __launch_bounds__(NT, 1)
void gru_fused(const float* __restrict__ x_gru,   // (T, 96)
               const float* __restrict__ x_lin,   // (T, 32)
               const float* __restrict__ h_init,  // (128,)
               const float* __restrict__ w_ih,    // (384, 96)
               const float* __restrict__ w_hh,    // (384, 128)
               const float* __restrict__ b_ih,    // (384,)
               const float* __restrict__ b_nv,    // (128,)
               const float* __restrict__ lbias_p, // (1,)
               float* __restrict__ out)           // (T, 1)
{
    __shared__ __align__(16) float sm[9024];
    __shared__ __align__(8) unsigned long long mbar_storage;
    const int tid = threadIdx.x;

    if (blockIdx.x != 0) {
        // ==== PRODUCER: igates = x_gru @ w_ih.T + b_ih, padded layout, r/z pre-halved ====
        const bool act  = (tid < 2 * G3);   // 768 active
        const int  b    = blockIdx.x - 1;   // 0..146
        const int  prow = tid >> 1;         // 0..383 (gate row)
        const int  kh   = tid & 1;          // k-half (48 each)
        float wreg[48];
        if (act) {
            const float* wp = w_ih + prow * INS + kh * 48;
            #pragma unroll
            for (int j = 0; j < 48; j++) wreg[j] = wp[j];
        }
        const float bih   = (act && kh == 0) ? b_ih[prow] : 0.0f;
        const float scale = (prow < 256) ? 0.5f : 1.0f;          // pre-halve r,z gates
        // padded store slot: [t][ (row & 127)*4 + gate ]
        const int slot = ((prow & 127) << 2) + (prow >> 7);

        for (int c = b; c < NCHUNK; c += NPROD) {
            const int t0 = c * CHUNK;
            __syncthreads();  // smem reuse guard across chunks
            for (int i = tid; i < CHUNK * INS; i += NT) {
                int ttl = i / INS, k = i % INS;
                sm[k * 9 + ttl] = x_gru[(size_t)(t0 + ttl) * INS + k];
            }
            __syncthreads();
            if (act) {
                float acc[CHUNK];
                #pragma unroll
                for (int ttl = 0; ttl < CHUNK; ttl++) acc[ttl] = bih;
                #pragma unroll 8
                for (int j = 0; j < 48; j++) {
                    const float w = wreg[j];
                    const float* xs = &sm[(kh * 48 + j) * 9];
                    #pragma unroll
                    for (int ttl = 0; ttl < CHUNK; ttl++)
                        acc[ttl] = fmaf(w, xs[ttl], acc[ttl]);
                }
                #pragma unroll
                for (int ttl = 0; ttl < CHUNK; ttl++)
                    acc[ttl] += __shfl_xor_sync(0xffffffffu, acc[ttl], 1);
                if (kh == 0) {
                    #pragma unroll
                    for (int ttl = 0; ttl < CHUNK; ttl++)
                        g_ig[(size_t)(t0 + ttl) * IGW + slot] = acc[ttl] * scale;
                }
            }
            __syncthreads();  // all stores issued before the release
            if (tid == 0) {
                __threadfence();
                atomicExch(&g_flag[c], 1);
            }
        }
        return;
    }

    // ==== SCAN: 1024 threads, row = wid*4 + (lane&3), kq = lane>>2 (broadcast-friendly) ====
    const int wid  = tid >> 5;               // 0..31
    const int lane = tid & 31;
    const int row  = wid * 4 + (lane & 3);   // 0..127
    const int kq   = lane >> 2;              // 16-wide K slice
    const bool is_outw = (wid == 8);         // deferred-output duty

    float* igb  = sm;            // [2][4096]
    float* xlb  = sm + 8192;     // [2][256]
    float* shA  = sm + 8704;     // padded h (160)
    float* shB  = sm + 8864;
    const unsigned mbar = smem_u32(&mbar_storage);

    // weights: 3 gates x 16 K = 8 f32x2 each; r,z pre-halved
    unsigned long long wr_[8], wz_[8], wn_[8];
    {
        const float2* p0 = (const float2*)(w_hh + (size_t)(row      ) * HID) + kq * 8;
        const float2* p1 = (const float2*)(w_hh + (size_t)(row + 128) * HID) + kq * 8;
        const float2* p2 = (const float2*)(w_hh + (size_t)(row + 256) * HID) + kq * 8;
        #pragma unroll
        for (int j = 0; j < 8; j++) { float2 v = p0[j]; wr_[j] = pk2(0.5f * v.x, 0.5f * v.y); }
        #pragma unroll
        for (int j = 0; j < 8; j++) { float2 v = p1[j]; wz_[j] = pk2(0.5f * v.x, 0.5f * v.y); }
        #pragma unroll
        for (int j = 0; j < 8; j++) { float2 v = p2[j]; wn_[j] = pk2(v.x, v.y); }
    }
    const float bn    = b_nv[row];
    const float lbias = lbias_p[0];
    float h_reg = h_init[row];
    if (kq == 0) shA[((row >> 4) * 20) + (row & 15)] = h_reg;
    float xl_reg = 0.0f;   // x_lin[t-1][lane] on warp 8

    // prologue: init mbar, kick copy of chunk 0
    if (tid == 0) {
        mbar_init(mbar, 1);
        wait_flag(&g_flag[0]);
        mbar_expect_tx(mbar, TX_BYTES);
        bulk_g2s(smem_u32(igb), g_ig, IG_CHUNK_BYTES, mbar);
        bulk_g2s(smem_u32(xlb), x_lin, XL_CHUNK_BYTES, mbar);
    }
    int flag_pre = 0;

    auto step = [&](int t, int s, const float* hrd, float* hwr,
                    const float* ig, const float* xl) {
        // ---- matvec: 3 gates over this thread's 16 h values ----
        unsigned long long ar = 0ull, az = 0ull, an2 = 0ull;
        const ulonglong2* h2 = (const ulonglong2*)(hrd + kq * 20);
        #pragma unroll
        for (int j = 0; j < 4; j++) {
            ulonglong2 v = h2[j];
            fma2(ar,  wr_[2 * j], v.x); fma2(ar,  wr_[2 * j + 1], v.y);
            fma2(az,  wz_[2 * j], v.x); fma2(az,  wz_[2 * j + 1], v.y);
            fma2(an2, wn_[2 * j], v.x); fma2(an2, wn_[2 * j + 1], v.y);
        }

        // deferred output for t-1 on warp 8 (hrd still holds h[t-1]; overlaps matvec)
        if (is_outw) {
            if (t > 0) {
                float p = hrd[((lane >> 4) * 20) + (lane & 15)] * xl_reg;
                p += __shfl_xor_sync(0xffffffffu, p, 1);
                p += __shfl_xor_sync(0xffffffffu, p, 2);
                p += __shfl_xor_sync(0xffffffffu, p, 4);
                p += __shfl_xor_sync(0xffffffffu, p, 8);
                p += __shfl_xor_sync(0xffffffffu, p, 16);
                if (lane == 0) out[t - 1] = p + lbias;
            }
            xl_reg = xl[s * LIN + lane];
        }

        // packed igates: one LDS.128 -> (r_half, z_half, n, pad)
        const float4 igq = *(const float4*)(ig + s * IGW + (row << 2));

        float gr = lo_hi_sum(ar), gz = lo_hi_sum(az), gn = lo_hi_sum(an2);
        gr += __shfl_xor_sync(0xffffffffu, gr, 4);
        gr += __shfl_xor_sync(0xffffffffu, gr, 8);
        gr += __shfl_xor_sync(0xffffffffu, gr, 16);
        gz += __shfl_xor_sync(0xffffffffu, gz, 4);
        gz += __shfl_xor_sync(0xffffffffu, gz, 8);
        gz += __shfl_xor_sync(0xffffffffu, gz, 16);
        gn += __shfl_xor_sync(0xffffffffu, gn, 4);
        gn += __shfl_xor_sync(0xffffffffu, gn, 8);
        gn += __shfl_xor_sync(0xffffffffu, gn, 16);

        // gates (redundant on 8 kq lanes; 3 MUFU)
        const float r    = sigmoid_half(gr + igq.x);
        const float z    = sigmoid_half(gz + igq.y);
        const float n    = tanh_fast(igq.z + r * (gn + bn));
        const float hnew = fmaf(z, h_reg - n, n);
        h_reg = hnew;
        if (kq == 0) hwr[((row >> 4) * 20) + (row & 15)] = hnew;
        __syncthreads();  // single barrier per step
    };

    for (int c = 0; c < NCHUNK; c++) {
        const float* ig = igb + (c & 1) * IG_CHUNK_F;
        const float* xl = xlb + (c & 1) * XL_CHUNK_F;

        if (tid == 0) mbar_wait(mbar, (unsigned)(c & 1));  // chunk c copy complete
        __syncthreads();                                   // publish buffer

        if (tid == 0 && c + 1 < NCHUNK) {
            if (flag_pre) asm volatile("fence.acq_rel.gpu;" ::: "memory");
            else          wait_flag(&g_flag[c + 1]);
            mbar_expect_tx(mbar, TX_BYTES);
            bulk_g2s(smem_u32(igb + ((c + 1) & 1) * IG_CHUNK_F),
                     g_ig + (size_t)(c + 1) * IG_CHUNK_F, IG_CHUNK_BYTES, mbar);
            bulk_g2s(smem_u32(xlb + ((c + 1) & 1) * XL_CHUNK_F),
                     x_lin + (size_t)(c + 1) * XL_CHUNK_F, XL_CHUNK_BYTES, mbar);
            flag_pre = (c + 2 < NCHUNK) ? ld_relaxed(&g_flag[c + 2]) : 1;
        }

        const int t0 = c * CHUNK;
        #pragma unroll 1
        for (int s = 0; s < CHUNK; s += 2) {
            step(t0 + s,     s,     shA, shB, ig, xl);
            step(t0 + s + 1, s + 1, shB, shA, ig, xl);
        }
    }

    // final output: shA holds h[TT-1]; xl_reg = x_lin[TT-1] on warp 8
    if (is_outw) {
        float p = shA[((lane >> 4) * 20) + (lane & 15)] * xl_reg;
        p += __shfl_xor_sync(0xffffffffu, p, 1);
        p += __shfl_xor_sync(0xffffffffu, p, 2);
        p += __shfl_xor_sync(0xffffffffu, p, 4);
        p += __shfl_xor_sync(0xffffffffu, p, 8);
        p += __shfl_xor_sync(0xffffffffu, p, 16);
        if (lane == 0) out[TT - 1] = p + lbias;
    }
}

extern "C" void kernel_launch(void* const* d_in, const int* in_sizes, int n_in,
                              void* d_out, int out_size) {
    const float* x_gru = (const float*)d_in[0];  // (65536, 96)
    const float* x_lin = (const float*)d_in[1];  // (65536, 32)
    const float* h0    = (const float*)d_in[2];  // (128,)
    const float* w_ih  = (const float*)d_in[3];  // (384, 96)
    const float* w_hh  = (const float*)d_in[4];  // (384, 128)
    const float* b_ih  = (const float*)d_in[5];  // (384,)
    const float* b_n   = (const float*)d_in[6];  // (128,)
    const float* lb    = (const float*)d_in[7];  // (1,)
    float* out = (float*)d_out;                  // (65536, 1)

    gru_clear_flags<<<(NCHUNK + 255) / 256, 256>>>();
    gru_fused<<<NBLK, NT>>>(x_gru, x_lin, h0, w_ih, w_hh, b_ih, b_n, lb, out);
}